// round 2
// baseline (speedup 1.0000x reference)
#include <cuda_runtime.h>
#include <cstdint>

// Problem constants (fixed by the dataset)
#define BB 4096
#define SS 50
#define DD 768
#define UU 768
#define QQ 200

// Scratch (device globals: allocation-free per harness rules)
__device__ float g_q[BB * QQ];   // relu(ue @ W1^T + b1)
__device__ float g_w[BB * DD];   // tanh(q @ W2^T + b2)

// ---------------------------------------------------------------------------
// GEMM: C[m][n] = act( sum_k A[m][k] * B[n][k] + bias[n] )
// A is [M,K] row-major, B is [N,K] row-major  ->  x @ W^T pattern.
// ACT: 0 = relu, 1 = tanh
// ---------------------------------------------------------------------------
template <int BM, int BN, int BK, int TM, int TN, int ACT>
__global__ void __launch_bounds__(256)
gemm_kt(const float* __restrict__ A, const float* __restrict__ B,
        const float* __restrict__ bias, float* __restrict__ C,
        int M, int N, int K)
{
    __shared__ float As[BK][BM];
    __shared__ float Bs[BK][BN];

    const int m0 = blockIdx.x * BM;
    const int n0 = blockIdx.y * BN;
    const int t  = threadIdx.x;

    const int tx = t % (BN / TN);
    const int ty = t / (BN / TN);

    float acc[TM][TN];
#pragma unroll
    for (int i = 0; i < TM; i++)
#pragma unroll
        for (int j = 0; j < TN; j++) acc[i][j] = 0.f;

    constexpr int ALOADS = (BM * BK) / (256 * 4);
    constexpr int BLOADS = (BN * BK) / (256 * 4);

    for (int k0 = 0; k0 < K; k0 += BK) {
#pragma unroll
        for (int r = 0; r < ALOADS; r++) {
            int idx = t + r * 256;
            int ml  = idx >> 2;
            int kq  = (idx & 3) * 4;
#pragma unroll
            for (int i = 0; i < 4; i++) {
                int kk = k0 + kq + i;
                As[kq + i][ml] = (kk < K) ? A[(size_t)(m0 + ml) * K + kk] : 0.f;
            }
        }
#pragma unroll
        for (int r = 0; r < BLOADS; r++) {
            int idx = t + r * 256;
            int nl  = idx >> 2;
            int kq  = (idx & 3) * 4;
            bool nok = (n0 + nl) < N;
#pragma unroll
            for (int i = 0; i < 4; i++) {
                int kk = k0 + kq + i;
                Bs[kq + i][nl] = (nok && kk < K) ? B[(size_t)(n0 + nl) * K + kk] : 0.f;
            }
        }
        __syncthreads();

#pragma unroll
        for (int k = 0; k < BK; k++) {
            float ra[TM], rb[TN];
#pragma unroll
            for (int i = 0; i < TM; i++) ra[i] = As[k][ty * TM + i];
#pragma unroll
            for (int j = 0; j < TN; j++) rb[j] = Bs[k][tx * TN + j];
#pragma unroll
            for (int i = 0; i < TM; i++)
#pragma unroll
                for (int j = 0; j < TN; j++) acc[i][j] += ra[i] * rb[j];
        }
        __syncthreads();
    }

#pragma unroll
    for (int i = 0; i < TM; i++) {
        int m = m0 + ty * TM + i;
#pragma unroll
        for (int j = 0; j < TN; j++) {
            int n = n0 + tx * TN + j;
            if (n < N) {
                float v = acc[i][j] + bias[n];
                v = (ACT == 0) ? fmaxf(v, 0.f) : tanhf(v);
                C[(size_t)m * N + n] = v;
            }
        }
    }
}

// ---------------------------------------------------------------------------
// Attention kernel: one CTA (512 threads) per batch row.
//
// Phase 1 (fused): each warp streams its rows of c from GMEM with float4
//   loads, simultaneously caching them to smem and accumulating the dot
//   product with the register-resident w row. c is read from HBM exactly
//   once; LDG->STS->FFMA chains from 16 warps keep HBM busy.
// Phase 2: warp 0 does the 50-wide softmax.
// Phase 3: out = c_smem * attn, coalesced float4 stores.
//
// SMEM: [0,256)          scores/attn (50 floats, padded)
//       [256, 153856)    c tile (50*768 floats = 150 KB)
// ---------------------------------------------------------------------------
#define ATTN_SMEM_BYTES 153856

__global__ void __launch_bounds__(512, 1)
attn_kernel(const float* __restrict__ c, const float* __restrict__ w,
            float* __restrict__ out)
{
    extern __shared__ __align__(16) unsigned char smem_raw[];
    float* attn_s = reinterpret_cast<float*>(smem_raw);
    float* c_s    = reinterpret_cast<float*>(smem_raw + 256);

    const int tid  = threadIdx.x;
    const int wi   = tid >> 5;
    const int lane = tid & 31;
    const int b    = blockIdx.x;

    // w row slice into registers: lane needs w4[lane + i*32], i = 0..5,
    // identical for every history row this warp processes.
    const float4* w4 = reinterpret_cast<const float4*>(w + (size_t)b * DD);
    float4 wr[6];
#pragma unroll
    for (int i = 0; i < 6; i++) wr[i] = __ldg(&w4[lane + i * 32]);

    // Phase 1: fused stream (GMEM -> smem) + dot product
    const float4* c4g = reinterpret_cast<const float4*>(c + (size_t)b * (SS * DD));
    float4* c4s = reinterpret_cast<float4*>(c_s);

#pragma unroll 1
    for (int s = wi; s < SS; s += 16) {
        const float4* crow = c4g + s * (DD / 4);
        float4*       srow = c4s + s * (DD / 4);
        float acc = 0.f;
#pragma unroll
        for (int i = 0; i < 6; i++) {
            float4 cv = crow[lane + i * 32];
            srow[lane + i * 32] = cv;
            acc += cv.x * wr[i].x + cv.y * wr[i].y + cv.z * wr[i].z + cv.w * wr[i].w;
        }
#pragma unroll
        for (int off = 16; off > 0; off >>= 1)
            acc += __shfl_xor_sync(0xFFFFFFFFu, acc, off);
        if (lane == 0) attn_s[s] = acc;
    }
    __syncthreads();

    // Phase 2: softmax over S = 50 (warp 0)
    if (tid < 32) {
        float v0 = attn_s[lane];
        float v1 = (lane + 32 < SS) ? attn_s[lane + 32] : -1e30f;
        float m = fmaxf(v0, v1);
#pragma unroll
        for (int off = 16; off > 0; off >>= 1)
            m = fmaxf(m, __shfl_xor_sync(0xFFFFFFFFu, m, off));
        float e0 = __expf(v0 - m);
        float e1 = (lane + 32 < SS) ? __expf(v1 - m) : 0.f;
        float sum = e0 + e1;
#pragma unroll
        for (int off = 16; off > 0; off >>= 1)
            sum += __shfl_xor_sync(0xFFFFFFFFu, sum, off);
        float inv = 1.f / sum;
        attn_s[lane] = e0 * inv;
        if (lane + 32 < SS) attn_s[lane + 32] = e1 * inv;
    }
    __syncthreads();

    // Phase 3: out = c * attn (from smem, coalesced float4 stores)
    float4* o4 = reinterpret_cast<float4*>(out) + (size_t)b * (SS * DD / 4);
#pragma unroll 4
    for (int i = tid; i < SS * DD / 4; i += 512) {
        int s = i / (DD / 4);
        float a = attn_s[s];
        float4 v = c4s[i];
        v.x *= a; v.y *= a; v.z *= a; v.w *= a;
        o4[i] = v;
    }
}

// ---------------------------------------------------------------------------
extern "C" void kernel_launch(void* const* d_in, const int* in_sizes, int n_in,
                              void* d_out, int out_size)
{
    const float* c   = (const float*)d_in[0];   // [B,S,D]
    const float* ue  = (const float*)d_in[1];   // [B,U]
    const float* W1  = (const float*)d_in[2];   // [Q,U]
    const float* b1  = (const float*)d_in[3];   // [Q]
    const float* W2  = (const float*)d_in[4];   // [D,Q]
    const float* b2  = (const float*)d_in[5];   // [D]
    float* out = (float*)d_out;

    float *qbuf = nullptr, *wbuf = nullptr;
    cudaGetSymbolAddress((void**)&qbuf, g_q);
    cudaGetSymbolAddress((void**)&wbuf, g_w);

    cudaFuncSetAttribute(attn_kernel,
                         cudaFuncAttributeMaxDynamicSharedMemorySize,
                         ATTN_SMEM_BYTES);

    // q = relu(ue @ W1^T + b1)     M=4096, N=200, K=768
    gemm_kt<128, 64, 16, 8, 4, 0><<<dim3(BB / 128, (QQ + 63) / 64), 256>>>(
        ue, W1, b1, qbuf, BB, QQ, UU);
    // w = tanh(q @ W2^T + b2)      M=4096, N=768, K=200
    gemm_kt<128, 64, 16, 8, 4, 1><<<dim3(BB / 128, DD / 64), 256>>>(
        qbuf, W2, b2, wbuf, BB, DD, QQ);
    // attention body
    attn_kernel<<<BB, 512, ATTN_SMEM_BYTES>>>(c, wbuf, out);
}

// round 3
// speedup vs baseline: 1.0130x; 1.0130x over previous
#include <cuda_runtime.h>
#include <cstdint>

// Problem constants (fixed by the dataset)
#define BB 4096
#define SS 50
#define DD 768
#define UU 768
#define QQ 200

// Scratch (device globals: allocation-free per harness rules)
__device__ float g_q[BB * QQ];   // relu(ue @ W1^T + b1)
__device__ float g_w[BB * DD];   // tanh(q @ W2^T + b2)

// ---------------------------------------------------------------------------
// GEMM: C[m][n] = act( sum_k A[m][k] * B[n][k] + bias[n] )
// A is [M,K] row-major, B is [N,K] row-major  ->  x @ W^T pattern.
// BM=BN=64, BK=16, TM=TN=4, 256 threads. Small tiles on purpose: the two
// MLP GEMMs are tiny (N=200 / K=200), so we need grid >> 148 and several
// CTAs per SM; Round-2 ncu showed grid=128 -> occ 12.5%, latency-bound.
// ACT: 0 = relu, 1 = tanh
// ---------------------------------------------------------------------------
#define GBM 64
#define GBN 64
#define GBK 16

template <int ACT>
__global__ void __launch_bounds__(256)
gemm_kt(const float* __restrict__ A, const float* __restrict__ B,
        const float* __restrict__ bias, float* __restrict__ C,
        int M, int N, int K)
{
    __shared__ float As[GBK][GBM];
    __shared__ float Bs[GBK][GBN];

    const int m0 = blockIdx.x * GBM;
    const int n0 = blockIdx.y * GBN;
    const int t  = threadIdx.x;

    const int tx = t & 15;    // 0..15 (N direction)
    const int ty = t >> 4;    // 0..15 (M direction)

    float acc[4][4];
#pragma unroll
    for (int i = 0; i < 4; i++)
#pragma unroll
        for (int j = 0; j < 4; j++) acc[i][j] = 0.f;

    // Tile-load indices: each thread loads one float4 of A and one of B.
    const int ml = t >> 2;          // 0..63
    const int kq = (t & 3) * 4;     // 0,4,8,12

    for (int k0 = 0; k0 < K; k0 += GBK) {
        // ---- A tile: As[k][m] (transpose on store) ----
        {
            float4 v;
            int kk = k0 + kq;
            const float* arow = A + (size_t)(m0 + ml) * K;
            if (kk + 3 < K) {
                v = *reinterpret_cast<const float4*>(arow + kk);
            } else {
                v.x = (kk + 0 < K) ? arow[kk + 0] : 0.f;
                v.y = (kk + 1 < K) ? arow[kk + 1] : 0.f;
                v.z = (kk + 2 < K) ? arow[kk + 2] : 0.f;
                v.w = (kk + 3 < K) ? arow[kk + 3] : 0.f;
            }
            As[kq + 0][ml] = v.x;
            As[kq + 1][ml] = v.y;
            As[kq + 2][ml] = v.z;
            As[kq + 3][ml] = v.w;
        }
        // ---- B tile: Bs[k][n] ----
        {
            float4 v = {0.f, 0.f, 0.f, 0.f};
            int kk = k0 + kq;
            if (n0 + ml < N) {
                const float* brow = B + (size_t)(n0 + ml) * K;
                if (kk + 3 < K) {
                    v = *reinterpret_cast<const float4*>(brow + kk);
                } else {
                    v.x = (kk + 0 < K) ? brow[kk + 0] : 0.f;
                    v.y = (kk + 1 < K) ? brow[kk + 1] : 0.f;
                    v.z = (kk + 2 < K) ? brow[kk + 2] : 0.f;
                    v.w = (kk + 3 < K) ? brow[kk + 3] : 0.f;
                }
            }
            Bs[kq + 0][ml] = v.x;
            Bs[kq + 1][ml] = v.y;
            Bs[kq + 2][ml] = v.z;
            Bs[kq + 3][ml] = v.w;
        }
        __syncthreads();

#pragma unroll
        for (int k = 0; k < GBK; k++) {
            float4 a = reinterpret_cast<const float4*>(&As[k][0])[ty];
            float4 b = reinterpret_cast<const float4*>(&Bs[k][0])[tx];
            acc[0][0] += a.x * b.x; acc[0][1] += a.x * b.y;
            acc[0][2] += a.x * b.z; acc[0][3] += a.x * b.w;
            acc[1][0] += a.y * b.x; acc[1][1] += a.y * b.y;
            acc[1][2] += a.y * b.z; acc[1][3] += a.y * b.w;
            acc[2][0] += a.z * b.x; acc[2][1] += a.z * b.y;
            acc[2][2] += a.z * b.z; acc[2][3] += a.z * b.w;
            acc[3][0] += a.w * b.x; acc[3][1] += a.w * b.y;
            acc[3][2] += a.w * b.z; acc[3][3] += a.w * b.w;
        }
        __syncthreads();
    }

    // Epilogue: bias + activation
#pragma unroll
    for (int i = 0; i < 4; i++) {
        int m = m0 + ty * 4 + i;
#pragma unroll
        for (int j = 0; j < 4; j++) {
            int n = n0 + tx * 4 + j;
            if (n < N) {
                float v = acc[i][j] + bias[n];
                v = (ACT == 0) ? fmaxf(v, 0.f) : tanhf(v);
                C[(size_t)m * N + n] = v;
            }
        }
    }
}

// ---------------------------------------------------------------------------
// Attention kernel: one CTA (512 threads) per batch row.
//
// Phase 1 (fused): each warp streams its rows of c from GMEM with float4
//   loads, simultaneously caching them to smem and accumulating the dot
//   product with the register-resident w row. c is read from HBM exactly
//   once.
// Phase 2: warp 0 does the 50-wide softmax.
// Phase 3: out = c_smem * attn, coalesced float4 stores.
//
// SMEM: [0,256)          scores/attn (50 floats, padded)
//       [256, 153856)    c tile (50*768 floats = 150 KB)
// ---------------------------------------------------------------------------
#define ATTN_SMEM_BYTES 153856

__global__ void __launch_bounds__(512, 1)
attn_kernel(const float* __restrict__ c, const float* __restrict__ w,
            float* __restrict__ out)
{
    extern __shared__ __align__(16) unsigned char smem_raw[];
    float* attn_s = reinterpret_cast<float*>(smem_raw);
    float* c_s    = reinterpret_cast<float*>(smem_raw + 256);

    const int tid  = threadIdx.x;
    const int wi   = tid >> 5;
    const int lane = tid & 31;
    const int b    = blockIdx.x;

    const float4* w4 = reinterpret_cast<const float4*>(w + (size_t)b * DD);
    float4 wr[6];
#pragma unroll
    for (int i = 0; i < 6; i++) wr[i] = __ldg(&w4[lane + i * 32]);

    // Phase 1: fused stream (GMEM -> smem) + dot product
    const float4* c4g = reinterpret_cast<const float4*>(c + (size_t)b * (SS * DD));
    float4* c4s = reinterpret_cast<float4*>(c_s);

#pragma unroll 1
    for (int s = wi; s < SS; s += 16) {
        const float4* crow = c4g + s * (DD / 4);
        float4*       srow = c4s + s * (DD / 4);
        float acc = 0.f;
#pragma unroll
        for (int i = 0; i < 6; i++) {
            float4 cv = crow[lane + i * 32];
            srow[lane + i * 32] = cv;
            acc += cv.x * wr[i].x + cv.y * wr[i].y + cv.z * wr[i].z + cv.w * wr[i].w;
        }
#pragma unroll
        for (int off = 16; off > 0; off >>= 1)
            acc += __shfl_xor_sync(0xFFFFFFFFu, acc, off);
        if (lane == 0) attn_s[s] = acc;
    }
    __syncthreads();

    // Phase 2: softmax over S = 50 (warp 0)
    if (tid < 32) {
        float v0 = attn_s[lane];
        float v1 = (lane + 32 < SS) ? attn_s[lane + 32] : -1e30f;
        float m = fmaxf(v0, v1);
#pragma unroll
        for (int off = 16; off > 0; off >>= 1)
            m = fmaxf(m, __shfl_xor_sync(0xFFFFFFFFu, m, off));
        float e0 = __expf(v0 - m);
        float e1 = (lane + 32 < SS) ? __expf(v1 - m) : 0.f;
        float sum = e0 + e1;
#pragma unroll
        for (int off = 16; off > 0; off >>= 1)
            sum += __shfl_xor_sync(0xFFFFFFFFu, sum, off);
        float inv = 1.f / sum;
        attn_s[lane] = e0 * inv;
        if (lane + 32 < SS) attn_s[lane + 32] = e1 * inv;
    }
    __syncthreads();

    // Phase 3: out = c * attn (from smem, coalesced float4 stores)
    float4* o4 = reinterpret_cast<float4*>(out) + (size_t)b * (SS * DD / 4);
#pragma unroll 4
    for (int i = tid; i < SS * DD / 4; i += 512) {
        int s = i / (DD / 4);
        float a = attn_s[s];
        float4 v = c4s[i];
        v.x *= a; v.y *= a; v.z *= a; v.w *= a;
        o4[i] = v;
    }
}

// ---------------------------------------------------------------------------
extern "C" void kernel_launch(void* const* d_in, const int* in_sizes, int n_in,
                              void* d_out, int out_size)
{
    const float* c   = (const float*)d_in[0];   // [B,S,D]
    const float* ue  = (const float*)d_in[1];   // [B,U]
    const float* W1  = (const float*)d_in[2];   // [Q,U]
    const float* b1  = (const float*)d_in[3];   // [Q]
    const float* W2  = (const float*)d_in[4];   // [D,Q]
    const float* b2  = (const float*)d_in[5];   // [D]
    float* out = (float*)d_out;

    float *qbuf = nullptr, *wbuf = nullptr;
    cudaGetSymbolAddress((void**)&qbuf, g_q);
    cudaGetSymbolAddress((void**)&wbuf, g_w);

    cudaFuncSetAttribute(attn_kernel,
                         cudaFuncAttributeMaxDynamicSharedMemorySize,
                         ATTN_SMEM_BYTES);

    // q = relu(ue @ W1^T + b1)     M=4096, N=200, K=768 -> grid 64x4 = 256
    gemm_kt<0><<<dim3(BB / GBM, (QQ + GBN - 1) / GBN), 256>>>(
        ue, W1, b1, qbuf, BB, QQ, UU);
    // w = tanh(q @ W2^T + b2)      M=4096, N=768, K=200 -> grid 64x12 = 768
    gemm_kt<1><<<dim3(BB / GBM, DD / GBN), 256>>>(
        qbuf, W2, b2, wbuf, BB, DD, QQ);
    // attention body
    attn_kernel<<<BB, 512, ATTN_SMEM_BYTES>>>(c, wbuf, out);
}

// round 4
// speedup vs baseline: 1.0215x; 1.0084x over previous
#include <cuda_runtime.h>
#include <cstdint>

// Problem constants (fixed by the dataset)
#define BB 4096
#define SS 50
#define DD 768
#define UU 768
#define QQ 200
#define QP 256   // Q padded to 256 so all GEMM dims divide evenly

// Scratch (device globals: allocation-free per harness rules)
__device__ float g_W1p[QP * UU];   // W1 zero-padded to [256, 768]
__device__ float g_b1p[QP];        // b1 zero-padded to [256]
__device__ float g_W2p[DD * QP];   // W2 zero-padded to [768, 256]
__device__ float g_qp[BB * QP];    // relu(ue @ W1p^T + b1p), stride 256
__device__ float g_w[BB * DD];     // tanh(q @ W2p^T + b2)

// ---------------------------------------------------------------------------
// Pad W1 [200,768]->[256,768], b1 [200]->[256], W2 [768,200]->[768,256]
// Padded rows/cols are zero => q_pad[200:256] = relu(0+0) = 0 and contributes
// nothing to GEMM2 (W2 pad cols zero). Mathematically exact.
// ---------------------------------------------------------------------------
__global__ void pad_weights(const float* __restrict__ W1, const float* __restrict__ b1,
                            const float* __restrict__ W2,
                            float* __restrict__ W1p, float* __restrict__ b1p,
                            float* __restrict__ W2p)
{
    int i = blockIdx.x * blockDim.x + threadIdx.x;
    if (i < QP * UU) {
        // W1 rows are contiguous: padding = tail zeros
        W1p[i] = (i < QQ * UU) ? W1[i] : 0.f;
        int c = i & (QP - 1);
        W2p[i] = (c < QQ) ? W2[(i >> 8) * QQ + c] : 0.f;
    }
    if (i < QP) b1p[i] = (i < QQ) ? b1[i] : 0.f;
}

// ---------------------------------------------------------------------------
// GEMM: C[m][n] = act( sum_k A[m][k] * B[n][k] + bias[n] )
// A: [M,K] row-major, B: [N,K] row-major  (x @ W^T pattern).
// BM=32, BN=64, BK=16, 128 threads, 4x4 microtile.
// Smem double-buffered; LDG of tile k+1 issued before compute of tile k;
// ONE __syncthreads per K-iteration. All dims divide evenly (Q padded).
// ACT: 0 = relu, 1 = tanh
// ---------------------------------------------------------------------------
#define GBM 32
#define GBN 64
#define GBK 16

template <int ACT>
__global__ void __launch_bounds__(128, 8)
gemm_db(const float* __restrict__ A, const float* __restrict__ B,
        const float* __restrict__ bias, float* __restrict__ C,
        int M, int N, int K)
{
    __shared__ float As[2][GBK][GBM];
    __shared__ float Bs[2][GBK][GBN];

    const int m0 = blockIdx.x * GBM;
    const int n0 = blockIdx.y * GBN;
    const int t  = threadIdx.x;
    const int tx = t & 15;    // N dir: 16 * TN=4 = 64
    const int ty = t >> 4;    // M dir:  8 * TM=4 = 32

    // Tile-load mapping: each thread owns 1 float4 of A, 2 float4 of B.
    const int ml = t >> 2;          // 0..31
    const int kq = (t & 3) * 4;     // 0,4,8,12

    const float* aptr  = A + (size_t)(m0 + ml) * K + kq;
    const float* bptr0 = B + (size_t)(n0 + ml) * K + kq;
    const float* bptr1 = B + (size_t)(n0 + ml + 32) * K + kq;

    float acc[4][4] = {};

    // Prologue: tile 0 -> buf 0
    float4 ar  = *reinterpret_cast<const float4*>(aptr);
    float4 br0 = *reinterpret_cast<const float4*>(bptr0);
    float4 br1 = *reinterpret_cast<const float4*>(bptr1);
    As[0][kq + 0][ml] = ar.x;  As[0][kq + 1][ml] = ar.y;
    As[0][kq + 2][ml] = ar.z;  As[0][kq + 3][ml] = ar.w;
    Bs[0][kq + 0][ml] = br0.x; Bs[0][kq + 1][ml] = br0.y;
    Bs[0][kq + 2][ml] = br0.z; Bs[0][kq + 3][ml] = br0.w;
    Bs[0][kq + 0][ml + 32] = br1.x; Bs[0][kq + 1][ml + 32] = br1.y;
    Bs[0][kq + 2][ml + 32] = br1.z; Bs[0][kq + 3][ml + 32] = br1.w;
    __syncthreads();

    const int kIters = K / GBK;
#pragma unroll 1
    for (int it = 0; it < kIters; it++) {
        const int cur = it & 1;
        // Prefetch next tile (LDG in flight across the compute block)
        if (it + 1 < kIters) {
            const int off = (it + 1) * GBK;
            ar  = *reinterpret_cast<const float4*>(aptr  + off);
            br0 = *reinterpret_cast<const float4*>(bptr0 + off);
            br1 = *reinterpret_cast<const float4*>(bptr1 + off);
        }
        // Compute on current buffer
#pragma unroll
        for (int k = 0; k < GBK; k++) {
            float4 a = *reinterpret_cast<const float4*>(&As[cur][k][ty * 4]);
            float4 b = *reinterpret_cast<const float4*>(&Bs[cur][k][tx * 4]);
            acc[0][0] += a.x * b.x; acc[0][1] += a.x * b.y;
            acc[0][2] += a.x * b.z; acc[0][3] += a.x * b.w;
            acc[1][0] += a.y * b.x; acc[1][1] += a.y * b.y;
            acc[1][2] += a.y * b.z; acc[1][3] += a.y * b.w;
            acc[2][0] += a.z * b.x; acc[2][1] += a.z * b.y;
            acc[2][2] += a.z * b.z; acc[2][3] += a.z * b.w;
            acc[3][0] += a.w * b.x; acc[3][1] += a.w * b.y;
            acc[3][2] += a.w * b.z; acc[3][3] += a.w * b.w;
        }
        // Stage next tile into the other buffer (safe: that buffer was last
        // read in iteration it-1, fully retired at the previous barrier)
        if (it + 1 < kIters) {
            const int nxt = cur ^ 1;
            As[nxt][kq + 0][ml] = ar.x;  As[nxt][kq + 1][ml] = ar.y;
            As[nxt][kq + 2][ml] = ar.z;  As[nxt][kq + 3][ml] = ar.w;
            Bs[nxt][kq + 0][ml] = br0.x; Bs[nxt][kq + 1][ml] = br0.y;
            Bs[nxt][kq + 2][ml] = br0.z; Bs[nxt][kq + 3][ml] = br0.w;
            Bs[nxt][kq + 0][ml + 32] = br1.x; Bs[nxt][kq + 1][ml + 32] = br1.y;
            Bs[nxt][kq + 2][ml + 32] = br1.z; Bs[nxt][kq + 3][ml + 32] = br1.w;
        }
        __syncthreads();
    }

    // Epilogue: bias + activation (all indices in range: dims padded)
#pragma unroll
    for (int i = 0; i < 4; i++) {
        int m = m0 + ty * 4 + i;
#pragma unroll
        for (int j = 0; j < 4; j++) {
            int n = n0 + tx * 4 + j;
            float v = acc[i][j] + bias[n];
            v = (ACT == 0) ? fmaxf(v, 0.f) : tanhf(v);
            C[(size_t)m * N + n] = v;
        }
    }
}

// ---------------------------------------------------------------------------
// Attention kernel: one CTA (512 threads) per batch row.  (unchanged from R2,
// near HBM roofline: c read from HBM exactly once via fused LDG->STS->dot.)
// ---------------------------------------------------------------------------
#define ATTN_SMEM_BYTES 153856

__global__ void __launch_bounds__(512, 1)
attn_kernel(const float* __restrict__ c, const float* __restrict__ w,
            float* __restrict__ out)
{
    extern __shared__ __align__(16) unsigned char smem_raw[];
    float* attn_s = reinterpret_cast<float*>(smem_raw);
    float* c_s    = reinterpret_cast<float*>(smem_raw + 256);

    const int tid  = threadIdx.x;
    const int wi   = tid >> 5;
    const int lane = tid & 31;
    const int b    = blockIdx.x;

    const float4* w4 = reinterpret_cast<const float4*>(w + (size_t)b * DD);
    float4 wr[6];
#pragma unroll
    for (int i = 0; i < 6; i++) wr[i] = __ldg(&w4[lane + i * 32]);

    const float4* c4g = reinterpret_cast<const float4*>(c + (size_t)b * (SS * DD));
    float4* c4s = reinterpret_cast<float4*>(c_s);

#pragma unroll 1
    for (int s = wi; s < SS; s += 16) {
        const float4* crow = c4g + s * (DD / 4);
        float4*       srow = c4s + s * (DD / 4);
        float acc = 0.f;
#pragma unroll
        for (int i = 0; i < 6; i++) {
            float4 cv = crow[lane + i * 32];
            srow[lane + i * 32] = cv;
            acc += cv.x * wr[i].x + cv.y * wr[i].y + cv.z * wr[i].z + cv.w * wr[i].w;
        }
#pragma unroll
        for (int off = 16; off > 0; off >>= 1)
            acc += __shfl_xor_sync(0xFFFFFFFFu, acc, off);
        if (lane == 0) attn_s[s] = acc;
    }
    __syncthreads();

    if (tid < 32) {
        float v0 = attn_s[lane];
        float v1 = (lane + 32 < SS) ? attn_s[lane + 32] : -1e30f;
        float m = fmaxf(v0, v1);
#pragma unroll
        for (int off = 16; off > 0; off >>= 1)
            m = fmaxf(m, __shfl_xor_sync(0xFFFFFFFFu, m, off));
        float e0 = __expf(v0 - m);
        float e1 = (lane + 32 < SS) ? __expf(v1 - m) : 0.f;
        float sum = e0 + e1;
#pragma unroll
        for (int off = 16; off > 0; off >>= 1)
            sum += __shfl_xor_sync(0xFFFFFFFFu, sum, off);
        float inv = 1.f / sum;
        attn_s[lane] = e0 * inv;
        if (lane + 32 < SS) attn_s[lane + 32] = e1 * inv;
    }
    __syncthreads();

    float4* o4 = reinterpret_cast<float4*>(out) + (size_t)b * (SS * DD / 4);
#pragma unroll 4
    for (int i = tid; i < SS * DD / 4; i += 512) {
        int s = i / (DD / 4);
        float a = attn_s[s];
        float4 v = c4s[i];
        v.x *= a; v.y *= a; v.z *= a; v.w *= a;
        o4[i] = v;
    }
}

// ---------------------------------------------------------------------------
extern "C" void kernel_launch(void* const* d_in, const int* in_sizes, int n_in,
                              void* d_out, int out_size)
{
    const float* c   = (const float*)d_in[0];   // [B,S,D]
    const float* ue  = (const float*)d_in[1];   // [B,U]
    const float* W1  = (const float*)d_in[2];   // [Q,U]
    const float* b1  = (const float*)d_in[3];   // [Q]
    const float* W2  = (const float*)d_in[4];   // [D,Q]
    const float* b2  = (const float*)d_in[5];   // [D]
    float* out = (float*)d_out;

    float *W1p, *b1p, *W2p, *qp, *wbuf;
    cudaGetSymbolAddress((void**)&W1p, g_W1p);
    cudaGetSymbolAddress((void**)&b1p, g_b1p);
    cudaGetSymbolAddress((void**)&W2p, g_W2p);
    cudaGetSymbolAddress((void**)&qp,  g_qp);
    cudaGetSymbolAddress((void**)&wbuf, g_w);

    cudaFuncSetAttribute(attn_kernel,
                         cudaFuncAttributeMaxDynamicSharedMemorySize,
                         ATTN_SMEM_BYTES);

    // Pad weights (tiny)
    pad_weights<<<(QP * UU + 255) / 256, 256>>>(W1, b1, W2, W1p, b1p, W2p);

    // q = relu(ue @ W1p^T + b1p)   M=4096, N=256, K=768 -> grid 128x4 = 512
    gemm_db<0><<<dim3(BB / GBM, QP / GBN), 128>>>(ue, W1p, b1p, qp, BB, QP, UU);
    // w = tanh(q @ W2p^T + b2)     M=4096, N=768, K=256 -> grid 128x12 = 1536
    gemm_db<1><<<dim3(BB / GBM, DD / GBN), 128>>>(qp, W2p, b2, wbuf, BB, DD, QP);
    // attention body
    attn_kernel<<<BB, 512, ATTN_SMEM_BYTES>>>(c, wbuf, out);
}